// round 15
// baseline (speedup 1.0000x reference)
#include <cuda_runtime.h>
#include <cstdint>
#include <math.h>

#define Bn 32
#define Cn 512
#define HWn 3136
#define NV4 784                       // HWn / 4
#define ROWS 4                        // rows per buffer
#define TPB 256
#define TPR 64                        // threads per row (2 warps)
#define BLKS_PER_BATCH (Cn / ROWS)    // 128
#define NGROUPS 2
#define NBLOCKS (NGROUPS * BLKS_PER_BATCH)  // 256 (2 per SM)
#define NPASS (Bn / NGROUPS)          // 16
#define BUF_ELEMS (ROWS * HWn)        // 12544 floats
#define SMEM_BYTES (2 * BUF_ELEMS * 4)  // 100352 B

__device__ float g_y[Bn * Cn];
__device__ int   g_cnt[Bn];

__global__ void init_kernel() {
    if (threadIdx.x < Bn) g_cnt[threadIdx.x] = 0;
}

__device__ __forceinline__ void cp_async16(unsigned int saddr, const void* gaddr) {
    asm volatile("cp.async.cg.shared.global [%0], [%1], 16;\n"
                 :: "r"(saddr), "l"(gaddr));
}

// Deformable-attention scalar for (b, p). __ldcg: L2-coherent reads of g_y.
__device__ __forceinline__ float attn_for(int b, int p,
                                          const float* __restrict__ wo,
                                          const float* __restrict__ wd,
                                          const float* __restrict__ bd) {
    const float* yb = g_y + b * Cn;
    float acc = bd[0];
    #pragma unroll
    for (int k = 0; k < 3; k++) {
        float off = 0.0f;
        #pragma unroll
        for (int jj = 0; jj < 3; jj++) {
            int ii = p + jj - 1;
            float yv = (ii >= 0 && ii < Cn) ? __ldcg(&yb[ii]) : 0.0f;
            off = fmaf(wo[k * 3 + jj], yv, off);
        }
        float pos = (float)(p + k - 1) + off;
        float p0 = floorf(pos);
        float frac = pos - p0;
        int p0i = (int)p0;
        float v0 = (p0i >= 0     && p0i < Cn)     ? __ldcg(&yb[p0i])     : 0.0f;
        float v1 = (p0i + 1 >= 0 && p0i + 1 < Cn) ? __ldcg(&yb[p0i + 1]) : 0.0f;
        acc = fmaf(wd[k], fmaf(v1 - v0, frac, v0), acc);
    }
    return 1.0f / (1.0f + __expf(-acc));
}

// Double-buffered cp.async pipeline: reads of pass p+1 stream into buffer B
// (no register dependency, no barrier gating) while pass p is summed from
// SMEM, the per-batch barrier clears, and pass p is scaled+written from
// buffer A. DRAM sees continuous mixed read+write traffic.
__global__ void __launch_bounds__(TPB, 2)
dca_kernel(const float* __restrict__ x, float* __restrict__ out,
           const float* __restrict__ w_offset,
           const float* __restrict__ w_deform,
           const float* __restrict__ b_deform) {
    extern __shared__ float smem[];          // [2][ROWS][HWn]
    __shared__ float part[2 * ROWS];
    __shared__ float sattn[ROWS];

    const int group = blockIdx.x / BLKS_PER_BATCH;   // 0..1
    const int j     = blockIdx.x % BLKS_PER_BATCH;   // 0..127
    const int warp  = threadIdx.x >> 5;
    const int lane  = threadIdx.x & 31;
    const int r     = warp >> 1;             // row in buffer: 0..3
    const int h     = warp & 1;
    const int tr    = h * 32 + lane;         // 0..63 within row

    const unsigned int smem_u32 = (unsigned int)__cvta_generic_to_shared(smem);

    // ---- prologue: issue reads for pass 0 ----
    {
        const int b0   = group;                      // pass 0 batch
        const int row0 = b0 * Cn + j * ROWS + r;
        const float4* rp = (const float4*)(x + (size_t)row0 * HWn);
        unsigned int sdst = smem_u32 + (unsigned int)(r * HWn) * 4u;
        for (int i = tr; i < NV4; i += TPR)
            cp_async16(sdst + (unsigned int)i * 16u, rp + i);
        asm volatile("cp.async.commit_group;\n");
    }

    for (int p = 0; p < NPASS; ++p) {
        const int buf = p & 1;
        const int b   = p * NGROUPS + group;
        const int c   = j * ROWS + r;
        const int row = b * Cn + c;

        // ---- issue next pass's reads into the other buffer ----
        if (p + 1 < NPASS) {
            const int b2   = (p + 1) * NGROUPS + group;
            const int row2 = b2 * Cn + j * ROWS + r;
            const float4* rp2 = (const float4*)(x + (size_t)row2 * HWn);
            unsigned int sdst = smem_u32
                          + (unsigned int)(((p + 1) & 1) * BUF_ELEMS + r * HWn) * 4u;
            for (int i = tr; i < NV4; i += TPR)
                cp_async16(sdst + (unsigned int)i * 16u, rp2 + i);
            asm volatile("cp.async.commit_group;\n");
            asm volatile("cp.async.wait_group 1;\n");   // pass p's data ready
        } else {
            asm volatile("cp.async.wait_group 0;\n");
        }
        __syncthreads();

        // ---- sum pass p's rows from SMEM (fast, SM-local) ----
        const float4* srow = (const float4*)(smem + buf * BUF_ELEMS + r * HWn);
        float s = 0.0f;
        #pragma unroll 4
        for (int i = tr; i < NV4; i += TPR) {
            float4 v = srow[i];
            s += (v.x + v.y) + (v.z + v.w);
        }
        #pragma unroll
        for (int o = 16; o > 0; o >>= 1)
            s += __shfl_down_sync(0xffffffffu, s, o);
        if (lane == 0) part[warp] = s;
        __syncthreads();
        if (tr == 0)
            g_y[row] = (part[2 * r] + part[2 * r + 1]) * (1.0f / (float)HWn);
        __syncthreads();

        // ---- per-batch barrier (gated only on peers' LDS sums) ----
        if (threadIdx.x == 0) {
            __threadfence();                 // publish g_y
            atomicAdd(&g_cnt[b], 1);
            while (atomicAdd(&g_cnt[b], 0) < BLKS_PER_BATCH) __nanosleep(32);
            __threadfence();                 // acquire
        }
        __syncthreads();

        // ---- attn + scale pass p from SMEM -> out ----
        if (tr == 0)
            sattn[r] = attn_for(b, c, w_offset, w_deform, b_deform);
        __syncthreads();
        const float a = sattn[r];

        float4* o4 = (float4*)(out + (size_t)row * HWn);
        #pragma unroll 4
        for (int i = tr; i < NV4; i += TPR) {
            float4 v = srow[i];
            v.x *= a; v.y *= a; v.z *= a; v.w *= a;
            o4[i] = v;
        }
        __syncthreads();   // buffer reused by cp.async two passes later
    }
}

extern "C" void kernel_launch(void* const* d_in, const int* in_sizes, int n_in,
                              void* d_out, int out_size) {
    const float* x        = (const float*)d_in[0];
    const float* w_offset = (const float*)d_in[1];
    const float* w_deform = (const float*)d_in[2];
    const float* b_deform = (const float*)d_in[3];
    float* out = (float*)d_out;

    cudaFuncSetAttribute(dca_kernel,
                         cudaFuncAttributeMaxDynamicSharedMemorySize, SMEM_BYTES);
    init_kernel<<<1, 32>>>();
    dca_kernel<<<NBLOCKS, TPB, SMEM_BYTES>>>(x, out, w_offset, w_deform, b_deform);
}

// round 16
// speedup vs baseline: 1.1326x; 1.1326x over previous
#include <cuda_runtime.h>
#include <math.h>

#define Bn 32
#define Cn 512
#define HWn 3136
#define NV4 784             // HWn / 4
#define NROWS (Bn * Cn)     // 16384
#define RETAIN_ROWS 6144    // 77 MB retained in L2 (safely < 126 MB)
#define RETAIN_START (NROWS - RETAIN_ROWS)   // 10240

__device__ float g_y[NROWS];

// ---------------------------------------------------------------------------
// Kernel 1: row means. Rows < RETAIN_START streamed (__ldcs, evict-first);
// tail rows plain loads so their lines are retained in L2 for kernel 2.
// ---------------------------------------------------------------------------
__global__ void mean_kernel(const float* __restrict__ x) {
    int warp = (blockIdx.x * blockDim.x + threadIdx.x) >> 5;
    int lane = threadIdx.x & 31;
    if (warp >= NROWS) return;
    const float4* row = (const float4*)(x + (size_t)warp * HWn);
    float s = 0.0f;
    if (warp < RETAIN_START) {
        #pragma unroll 4
        for (int i = lane; i < NV4; i += 32) {
            float4 v = __ldcs(&row[i]);
            s += (v.x + v.y) + (v.z + v.w);
        }
    } else {
        #pragma unroll 4
        for (int i = lane; i < NV4; i += 32) {
            float4 v = __ldg(&row[i]);      // retain in L2
            s += (v.x + v.y) + (v.z + v.w);
        }
    }
    #pragma unroll
    for (int o = 16; o > 0; o >>= 1)
        s += __shfl_down_sync(0xffffffffu, s, o);
    if (lane == 0) g_y[warp] = s * (1.0f / (float)HWn);
}

// ---------------------------------------------------------------------------
// Deformable-attention scalar for one row. L1D is flushed at launch, so plain
// loads of g_y are coherent with kernel 1's writes.
// ---------------------------------------------------------------------------
__device__ __forceinline__ float attn_for_row(int row,
                                              const float* __restrict__ wo,
                                              const float* __restrict__ wd,
                                              const float* __restrict__ bd) {
    int b = row >> 9;
    int p = row & (Cn - 1);
    const float* yb = g_y + b * Cn;
    float acc = bd[0];
    #pragma unroll
    for (int k = 0; k < 3; k++) {
        float off = 0.0f;
        #pragma unroll
        for (int jj = 0; jj < 3; jj++) {
            int ii = p + jj - 1;
            float yv = (ii >= 0 && ii < Cn) ? yb[ii] : 0.0f;
            off = fmaf(wo[k * 3 + jj], yv, off);
        }
        float pos = (float)(p + k - 1) + off;
        float p0 = floorf(pos);
        float frac = pos - p0;
        int p0i = (int)p0;
        float v0 = (p0i >= 0     && p0i < Cn)     ? yb[p0i]     : 0.0f;
        float v1 = (p0i + 1 >= 0 && p0i + 1 < Cn) ? yb[p0i + 1] : 0.0f;
        acc = fmaf(wd[k], fmaf(v1 - v0, frac, v0), acc);
    }
    return 1.0f / (1.0f + __expf(-acc));
}

// ---------------------------------------------------------------------------
// Kernel 2: out = attn * x in REVERSE row order. The first ~5 waves consume
// the 77 MB retained tail as L2 hits; remaining rows stream from DRAM.
// __ldcs demotes consumed lines; __stcs keeps writes from evicting the tail.
// ---------------------------------------------------------------------------
__global__ void scale_kernel(const float* __restrict__ x,
                             float* __restrict__ out,
                             const float* __restrict__ w_offset,
                             const float* __restrict__ w_deform,
                             const float* __restrict__ b_deform) {
    int row = (NROWS - 1) - blockIdx.x;     // reverse order
    __shared__ float sa;
    if (threadIdx.x == 0)
        sa = attn_for_row(row, w_offset, w_deform, b_deform);
    __syncthreads();
    float a = sa;

    const float4* xin = (const float4*)(x + (size_t)row * HWn);
    float4* o = (float4*)(out + (size_t)row * HWn);
    #pragma unroll 2
    for (int i = threadIdx.x; i < NV4; i += 256) {
        float4 v = __ldcs(&xin[i]);         // hit for tail rows; demote after
        v.x *= a; v.y *= a; v.z *= a; v.w *= a;
        __stcs(&o[i], v);                   // don't evict retained x
    }
}

extern "C" void kernel_launch(void* const* d_in, const int* in_sizes, int n_in,
                              void* d_out, int out_size) {
    const float* x        = (const float*)d_in[0];
    const float* w_offset = (const float*)d_in[1];
    const float* w_deform = (const float*)d_in[2];
    const float* b_deform = (const float*)d_in[3];
    float* out = (float*)d_out;

    mean_kernel<<<NROWS / 8, 256>>>(x);
    scale_kernel<<<NROWS, 256>>>(x, out, w_offset, w_deform, b_deform);
}